// round 9
// baseline (speedup 1.0000x reference)
#include <cuda_runtime.h>

#define NUM_CODES 1024
#define TPB  128
#define HPAD 5                 // each hist bin on its own 128B line
#define BATCH 4                // independent row-pairs in flight per warp
#define PAIRS_PER_WARP 16      // 32 rows per warp
#define ROWS_PER_BLOCK ((TPB / 32) * PAIRS_PER_WARP * 2)   // 128

__device__ int g_hist[NUM_CODES << HPAD];   // zero at load
__device__ unsigned int g_done;             // zero at load

// ---------------------------------------------------------------------------
// Warp-cooperative FSQ, no smem staging, no block barriers in the hot path.
// 16 lanes per row; every global access is a contiguous 512B warp transaction.
// BATCH independent pairs per step give each warp 4 LDG.128 (2KB) in flight.
// ---------------------------------------------------------------------------
__global__ __launch_bounds__(TPB, 6) void fsq_main(
    const float4* __restrict__ ze4,    // (B*16) float4
    const float4* __restrict__ Win4,   // 4 rows x 16 float4
    const float4* __restrict__ Wout4,  // 64 rows x 1 float4
    float4* __restrict__ zq4,          // (B*16) float4
    float* __restrict__ idx_out,       // (B,)
    float* __restrict__ scal,          // 4 scalars
    float invB)
{
    const int t    = threadIdx.x;
    const int lane = t & 31;
    const int warp = t >> 5;
    const int p    = lane & 15;            // float4 column within the row
    const int bit0 = lane & 1;
    const int bit1 = (lane >> 1) & 1;
    const int j_own = (bit0 << 1) | bit1;  // dim this lane finalizes

    // loop-invariant weights in registers (lane-indexed) — no LDS in the loop
    const float4 w0 = Win4[0 * 16 + p];
    const float4 w1 = Win4[1 * 16 + p];
    const float4 w2 = Win4[2 * 16 + p];
    const float4 w3 = Win4[3 * 16 + p];
    const float4 q0 = Wout4[4 * p + 0];
    const float4 q1 = Wout4[4 * p + 1];
    const float4 q2 = Wout4[4 * p + 2];
    const float4 q3 = Wout4[4 * p + 3];

    const float Lm1_own  = (j_own == 3) ? 1.0f : 7.0f;
    const float half_own = 0.5f * Lm1_own;
    const int   g4       = lane & ~3;      // 4-lane dim group base

    const unsigned int warpRowBase =
        (unsigned int)blockIdx.x * ROWS_PER_BLOCK + warp * (PAIRS_PER_WARP * 2);

    #pragma unroll 1
    for (int b = 0; b < PAIRS_PER_WARP / BATCH; ++b) {
        const unsigned int base = warpRowBase + b * (BATCH * 2);

        // ---- batch loads: BATCH independent contiguous 512B transactions ----
        float4 v[BATCH];
        #pragma unroll
        for (int j = 0; j < BATCH; ++j)
            v[j] = __ldcs(&ze4[(size_t)(base + 2 * j) * 16 + lane]);

        // ---- BATCH independent compute/store chains ----
        #pragma unroll
        for (int j = 0; j < BATCH; ++j) {
            const unsigned int pairBase = base + 2 * j;

            float a0 = fmaf(v[j].x, w0.x, fmaf(v[j].y, w0.y, fmaf(v[j].z, w0.z, v[j].w * w0.w)));
            float a1 = fmaf(v[j].x, w1.x, fmaf(v[j].y, w1.y, fmaf(v[j].z, w1.z, v[j].w * w1.w)));
            float a2 = fmaf(v[j].x, w2.x, fmaf(v[j].y, w2.y, fmaf(v[j].z, w2.z, v[j].w * w2.w)));
            float a3 = fmaf(v[j].x, w3.x, fmaf(v[j].y, w3.y, fmaf(v[j].z, w3.z, v[j].w * w3.w)));

            // dim-partitioned reduction across the 16-lane row group (5 SHFL)
            float r1 = __shfl_xor_sync(0xFFFFFFFFu, bit0 ? a0 : a2, 1);
            float r2 = __shfl_xor_sync(0xFFFFFFFFu, bit0 ? a1 : a3, 1);
            float kA = (bit0 ? a2 : a0) + r1;
            float kB = (bit0 ? a3 : a1) + r2;
            float r3 = __shfl_xor_sync(0xFFFFFFFFu, bit1 ? kA : kB, 2);
            float s  = (bit1 ? kB : kA) + r3;
            s += __shfl_xor_sync(0xFFFFFFFFu, s, 4);
            s += __shfl_xor_sync(0xFFFFFFFFu, s, 8);

            // quantize own dim (round-half-even == jnp.round)
            float u = (tanhf(s) + 1.0f) * 0.5f;
            float q = rintf(u * Lm1_own);
            q = fminf(fmaxf(q, 0.0f), Lm1_own);
            const float c_own = q - half_own;

            // broadcast centered values; dim d lives at group lane {0,2,1,3}
            const float c0 = __shfl_sync(0xFFFFFFFFu, c_own, g4 + 0);
            const float c1 = __shfl_sync(0xFFFFFFFFu, c_own, g4 + 2);
            const float c2 = __shfl_sync(0xFFFFFFFFu, c_own, g4 + 1);
            const float c3 = __shfl_sync(0xFFFFFFFFu, c_own, g4 + 3);

            // index + histogram (one lane per row: lanes 0 and 16)
            if (p == 0) {
                int i0 = __float2int_rn(c0 + 3.5f);
                int i1 = __float2int_rn(c1 + 3.5f);
                int i2 = __float2int_rn(c2 + 3.5f);
                int i3 = __float2int_rn(c3 + 0.5f);
                int index = i0 + (i1 << 3) + (i2 << 6) + (i3 << 9);
                __stcs(&idx_out[pairBase + (lane >> 4)], (float)index);
                atomicAdd(&g_hist[index << HPAD], 1);
            }

            // out-projection: this lane's 4 output elements
            float4 o;
            o.x = fmaf(c0, q0.x, fmaf(c1, q0.y, fmaf(c2, q0.z, c3 * q0.w)));
            o.y = fmaf(c0, q1.x, fmaf(c1, q1.y, fmaf(c2, q1.z, c3 * q1.w)));
            o.z = fmaf(c0, q2.x, fmaf(c1, q2.y, fmaf(c2, q2.z, c3 * q2.w)));
            o.w = fmaf(c0, q3.x, fmaf(c1, q3.y, fmaf(c2, q3.z, c3 * q3.w)));
            __stcs(&zq4[(size_t)pairBase * 16 + lane], o);   // contiguous 512B
        }
    }

    // ---- last-block finalize (fused; no second launch) ----
    __shared__ float red[8];
    __shared__ bool  isLast;
    __threadfence();
    if (t == 0) {
        unsigned int v = atomicAdd(&g_done, 1u);
        isLast = (v == gridDim.x - 1);
    }
    __syncthreads();
    if (!isLast) return;

    __threadfence();   // acquire: all blocks' hist atomics visible
    float term = 0.f, nz = 0.f;
    #pragma unroll
    for (int i = t; i < NUM_CODES; i += TPB) {
        int cnt = g_hist[i << HPAD];
        g_hist[i << HPAD] = 0;                        // reset for next replay
        float prob = (float)cnt * invB;
        term += prob * logf(prob + 1e-10f);
        nz   += (cnt > 0) ? 1.0f : 0.0f;
    }
    #pragma unroll
    for (int o = 16; o > 0; o >>= 1) {
        term += __shfl_down_sync(0xFFFFFFFFu, term, o);
        nz   += __shfl_down_sync(0xFFFFFFFFu, nz, o);
    }
    if ((t & 31) == 0) { red[t >> 5] = term; red[4 + (t >> 5)] = nz; }
    __syncthreads();
    if (t == 0) {
        float ssum = red[0] + red[1] + red[2] + red[3];
        float snz  = red[4] + red[5] + red[6] + red[7];
        scal[0] = 0.0f;                    // commitment_loss
        scal[1] = 0.0f;                    // codebook_loss
        scal[2] = expf(-ssum);             // perplexity
        scal[3] = snz * (1.0f / 1024.0f);  // utilization
        g_done = 0;                        // reset for next replay
    }
}

// ---------------------------------------------------------------------------
extern "C" void kernel_launch(void* const* d_in, const int* in_sizes, int n_in,
                              void* d_out, int out_size) {
    const float* ze   = (const float*)d_in[0];  // (B, 64)
    const float* Win  = (const float*)d_in[1];  // (4, 64)
    const float* Wout = (const float*)d_in[2];  // (64, 4)

    const int B = in_sizes[0] / 64;
    float* out  = (float*)d_out;
    float* zq   = out;                       // B*64
    float* idxf = out + (size_t)B * 64;      // B
    float* scal = idxf + B;                  // 4 scalars

    const int grid = B / ROWS_PER_BLOCK;     // 524288 / 128 = 4096

    fsq_main<<<grid, TPB>>>(
        (const float4*)ze, (const float4*)Win, (const float4*)Wout,
        (float4*)zq, idxf, scal, 1.0f / (float)B);
}

// round 10
// speedup vs baseline: 1.2420x; 1.2420x over previous
#include <cuda_runtime.h>

#define NUM_CODES 1024
#define TPB 128          // threads per block == rows per tile
#define HPAD 5           // each hist bin on its own 128B line

// XOR-swizzled tile: float4 slot for (row r, chunk c) = r*16 + (c ^ (r & 7)).
// Conflict-free for coalesced staged writes AND per-row reads, no padding.
#define TILE_F4 (TPB * 16)

__device__ int g_hist[NUM_CODES << HPAD];   // zero at load
__device__ unsigned int g_done;             // zero at load

// ---------------------------------------------------------------------------
// Single fused kernel. Block = 128 threads = 128 rows, 32KB swizzled tile
// -> 6 blocks/SM (24 warps) for latency hiding.
// cp.async rows into shared (coalesced, L2-only), compute 4 centered codes
// per row, regenerate outputs on the fly during the coalesced stage-out.
// Last block computes perplexity/utilization and resets global state.
// ---------------------------------------------------------------------------
__global__ __launch_bounds__(TPB, 6) void fsq_main(
    const float* __restrict__ ze,    // (B, 64)
    const float* __restrict__ Win,   // (4, 64) row-major
    const float4* __restrict__ Wout4,// (64) float4 rows
    float* __restrict__ zq,          // (B, 64)
    float* __restrict__ idx_out,     // (B,)
    float* __restrict__ scal,        // 4 scalars
    float invB)
{
    __shared__ float4 tile[TILE_F4];     // 32768 B swizzled input tile
    __shared__ float  sWin[256];         // 4 x 64
    __shared__ float4 sC[TPB];           // 4 centered codes per row (2 KB)
    __shared__ bool   isLast;
    __shared__ float  red[8];

    const int t = threadIdx.x;
    #pragma unroll
    for (int i = t; i < 256; i += TPB) sWin[i] = Win[i];

    const unsigned int rowBase = (unsigned int)blockIdx.x * TPB;

    // ---- stage in: 128 rows x 16 float4 via cp.async.cg (L2-only) ----
    const float4* gin = reinterpret_cast<const float4*>(ze) + (size_t)rowBase * 16;
    #pragma unroll
    for (int i = 0; i < 16; i++) {
        int f = t + i * TPB;            // global float4 index within tile
        int r = f >> 4, c = f & 15;
        int slot = (r << 4) | (c ^ (r & 7));
        unsigned int dst = (unsigned int)__cvta_generic_to_shared(&tile[slot]);
        asm volatile("cp.async.cg.shared.global [%0], [%1], 16;\n"
                     :: "r"(dst), "l"(gin + f) : "memory");
    }
    asm volatile("cp.async.commit_group;\n" ::: "memory");
    asm volatile("cp.async.wait_group 0;\n" ::: "memory");
    __syncthreads();

    // ---- compute: thread t owns row t ----
    {
        const float4* w0 = reinterpret_cast<const float4*>(sWin);
        const float4* w1 = reinterpret_cast<const float4*>(sWin + 64);
        const float4* w2 = reinterpret_cast<const float4*>(sWin + 128);
        const float4* w3 = reinterpret_cast<const float4*>(sWin + 192);
        const int rbase = t << 4;
        const int rx    = t & 7;

        float a0 = 0.f, a1 = 0.f, a2 = 0.f, a3 = 0.f;
        #pragma unroll
        for (int k = 0; k < 16; k++) {
            float4 v  = tile[rbase | (k ^ rx)];
            float4 x0 = w0[k], x1 = w1[k], x2 = w2[k], x3 = w3[k];
            a0 = fmaf(v.x, x0.x, fmaf(v.y, x0.y, fmaf(v.z, x0.z, fmaf(v.w, x0.w, a0))));
            a1 = fmaf(v.x, x1.x, fmaf(v.y, x1.y, fmaf(v.z, x1.z, fmaf(v.w, x1.w, a1))));
            a2 = fmaf(v.x, x2.x, fmaf(v.y, x2.y, fmaf(v.z, x2.z, fmaf(v.w, x2.w, a2))));
            a3 = fmaf(v.x, x3.x, fmaf(v.y, x3.y, fmaf(v.z, x3.z, fmaf(v.w, x3.w, a3))));
        }

        // FSQ quantize: levels (8,8,8,2), strides (1,8,64,512)
        const float acc[4] = {a0, a1, a2, a3};
        const float Lm1[4] = {7.f, 7.f, 7.f, 1.f};
        const int   str[4] = {1, 8, 64, 512};
        float c[4];
        int index = 0;
        #pragma unroll
        for (int j = 0; j < 4; j++) {
            float u = (tanhf(acc[j]) + 1.0f) * 0.5f;
            float s = u * Lm1[j];
            float r = rintf(s);                       // round-half-even == jnp.round
            r = fminf(fmaxf(r, 0.0f), Lm1[j]);
            index += (int)r * str[j];
            c[j] = r - Lm1[j] * 0.5f;
        }

        __stcs(&idx_out[rowBase + t], (float)index);  // coalesced streaming STG.32
        atomicAdd(&g_hist[index << HPAD], 1);         // 1 bin per 128B line

        sC[t] = make_float4(c[0], c[1], c[2], c[3]);  // 16B per row
    }
    __syncthreads();

    // ---- stage out: regenerate outputs, fully coalesced, streaming ----
    // f = t + i*TPB: column group f&15 == t&15 (constant), row r = f>>4 varies.
    {
        const int cgrp = t & 15;
        const float4 q0 = Wout4[4 * cgrp + 0];
        const float4 q1 = Wout4[4 * cgrp + 1];
        const float4 q2 = Wout4[4 * cgrp + 2];
        const float4 q3 = Wout4[4 * cgrp + 3];

        float4* gout = reinterpret_cast<float4*>(zq) + (size_t)rowBase * 16;
        #pragma unroll
        for (int i = 0; i < 16; i++) {
            int f = t + i * TPB;
            int r = f >> 4;
            float4 cr = sC[r];                 // broadcast LDS.128 (2 rows per warp)
            float4 o;
            o.x = fmaf(cr.x, q0.x, fmaf(cr.y, q0.y, fmaf(cr.z, q0.z, cr.w * q0.w)));
            o.y = fmaf(cr.x, q1.x, fmaf(cr.y, q1.y, fmaf(cr.z, q1.z, cr.w * q1.w)));
            o.z = fmaf(cr.x, q2.x, fmaf(cr.y, q2.y, fmaf(cr.z, q2.z, cr.w * q2.w)));
            o.w = fmaf(cr.x, q3.x, fmaf(cr.y, q3.y, fmaf(cr.z, q3.z, cr.w * q3.w)));
            __stcs(&gout[f], o);
        }
    }

    // ---- last-block finalize (fused; no second launch) ----
    __threadfence();
    if (t == 0) {
        unsigned int v = atomicAdd(&g_done, 1u);
        isLast = (v == gridDim.x - 1);
    }
    __syncthreads();
    if (!isLast) return;

    __threadfence();   // acquire: all blocks' hist atomics visible
    float term = 0.f, nz = 0.f;
    #pragma unroll
    for (int i = t; i < NUM_CODES; i += TPB) {
        int cnt = g_hist[i << HPAD];
        g_hist[i << HPAD] = 0;                        // reset for next replay
        float p = (float)cnt * invB;
        term += p * logf(p + 1e-10f);
        nz   += (cnt > 0) ? 1.0f : 0.0f;
    }
    #pragma unroll
    for (int o = 16; o > 0; o >>= 1) {
        term += __shfl_down_sync(0xFFFFFFFFu, term, o);
        nz   += __shfl_down_sync(0xFFFFFFFFu, nz, o);
    }
    if ((t & 31) == 0) { red[t >> 5] = term; red[4 + (t >> 5)] = nz; }
    __syncthreads();
    if (t == 0) {
        float s = red[0] + red[1] + red[2] + red[3];
        float n = red[4] + red[5] + red[6] + red[7];
        scal[0] = 0.0f;                  // commitment_loss
        scal[1] = 0.0f;                  // codebook_loss
        scal[2] = expf(-s);              // perplexity
        scal[3] = n * (1.0f / 1024.0f);  // utilization
        g_done = 0;                      // reset for next replay
    }
}

// ---------------------------------------------------------------------------
extern "C" void kernel_launch(void* const* d_in, const int* in_sizes, int n_in,
                              void* d_out, int out_size) {
    const float* ze   = (const float*)d_in[0];  // (B, 64)
    const float* Win  = (const float*)d_in[1];  // (4, 64)
    const float* Wout = (const float*)d_in[2];  // (64, 4)

    const int B = in_sizes[0] / 64;
    float* out  = (float*)d_out;
    float* zq   = out;                       // B*64
    float* idxf = out + (size_t)B * 64;      // B
    float* scal = idxf + B;                  // 4 scalars

    const int grid = B / TPB;                // 524288 / 128 = 4096

    fsq_main<<<grid, TPB>>>(ze, Win, (const float4*)Wout,
                            zq, idxf, scal, 1.0f / (float)B);
}

// round 11
// speedup vs baseline: 1.2427x; 1.0006x over previous
#include <cuda_runtime.h>

#define NUM_CODES 1024
#define TPB 128          // 4 warps; each warp owns an independent 32-row tile
#define HPAD 5           // each hist bin on its own 128B line
#define WROWS 32         // rows per warp-tile

__device__ int g_hist[NUM_CODES << HPAD];   // zero at load
__device__ unsigned int g_done;             // zero at load

// ---------------------------------------------------------------------------
// Warp-independent pipelines: each warp stages its own 8KB sub-tile with
// cp.async, waits on its own group (__syncwarp only), computes 32 rows
// thread-per-row, and streams out. No __syncthreads in the hot path ->
// 24 independently staggered warp-pipelines per SM keep DRAM queues full.
// ---------------------------------------------------------------------------
__global__ __launch_bounds__(TPB, 6) void fsq_main(
    const float* __restrict__ ze,    // (B, 64)
    const float* __restrict__ Win,   // (4, 64) row-major
    const float4* __restrict__ Wout4,// (64) float4 rows
    float* __restrict__ zq,          // (B, 64)
    float* __restrict__ idx_out,     // (B,)
    float* __restrict__ scal,        // 4 scalars
    float invB)
{
    __shared__ float4 tile[4][WROWS * 16];   // 4 x 8KB swizzled sub-tiles
    __shared__ float  sWin[256];             // 4 x 64
    __shared__ float4 sC[4][WROWS];          // centered codes per warp
    __shared__ bool   isLast;
    __shared__ float  red[8];

    const int t    = threadIdx.x;
    const int lane = t & 31;
    const int warp = t >> 5;

    #pragma unroll
    for (int i = t; i < 256; i += TPB) sWin[i] = Win[i];
    __syncthreads();                         // weights visible to all warps

    const unsigned int rowBase =
        ((unsigned int)blockIdx.x * 4 + warp) * WROWS;

    // ---- stage in (per warp): 32 rows x 16 float4 via cp.async.cg ----
    const float4* gin = reinterpret_cast<const float4*>(ze) + (size_t)rowBase * 16;
    #pragma unroll
    for (int i = 0; i < 16; i++) {
        int f = lane + i * 32;               // float4 index within warp-tile
        int r = f >> 4, c = f & 15;
        int slot = (r << 4) | (c ^ (r & 7)); // conflict-free swizzle
        unsigned int dst = (unsigned int)__cvta_generic_to_shared(&tile[warp][slot]);
        asm volatile("cp.async.cg.shared.global [%0], [%1], 16;\n"
                     :: "r"(dst), "l"(gin + f) : "memory");
    }
    asm volatile("cp.async.commit_group;\n" ::: "memory");
    asm volatile("cp.async.wait_group 0;\n" ::: "memory");
    __syncwarp();

    // ---- compute: lane owns row (rowBase + lane) ----
    {
        const float4* w0 = reinterpret_cast<const float4*>(sWin);
        const float4* w1 = reinterpret_cast<const float4*>(sWin + 64);
        const float4* w2 = reinterpret_cast<const float4*>(sWin + 128);
        const float4* w3 = reinterpret_cast<const float4*>(sWin + 192);
        const int rbase = lane << 4;
        const int rx    = lane & 7;

        float a0 = 0.f, a1 = 0.f, a2 = 0.f, a3 = 0.f;
        #pragma unroll
        for (int k = 0; k < 16; k++) {
            float4 v  = tile[warp][rbase | (k ^ rx)];
            float4 x0 = w0[k], x1 = w1[k], x2 = w2[k], x3 = w3[k];
            a0 = fmaf(v.x, x0.x, fmaf(v.y, x0.y, fmaf(v.z, x0.z, fmaf(v.w, x0.w, a0))));
            a1 = fmaf(v.x, x1.x, fmaf(v.y, x1.y, fmaf(v.z, x1.z, fmaf(v.w, x1.w, a1))));
            a2 = fmaf(v.x, x2.x, fmaf(v.y, x2.y, fmaf(v.z, x2.z, fmaf(v.w, x2.w, a2))));
            a3 = fmaf(v.x, x3.x, fmaf(v.y, x3.y, fmaf(v.z, x3.z, fmaf(v.w, x3.w, a3))));
        }

        // FSQ quantize: levels (8,8,8,2), strides (1,8,64,512)
        const float acc[4] = {a0, a1, a2, a3};
        const float Lm1[4] = {7.f, 7.f, 7.f, 1.f};
        const int   str[4] = {1, 8, 64, 512};
        float c[4];
        int index = 0;
        #pragma unroll
        for (int j = 0; j < 4; j++) {
            float u = (tanhf(acc[j]) + 1.0f) * 0.5f;
            float s = u * Lm1[j];
            float r = rintf(s);                       // round-half-even == jnp.round
            r = fminf(fmaxf(r, 0.0f), Lm1[j]);
            index += (int)r * str[j];
            c[j] = r - Lm1[j] * 0.5f;
        }

        __stcs(&idx_out[rowBase + lane], (float)index);  // coalesced STG.32
        atomicAdd(&g_hist[index << HPAD], 1);            // 1 bin per 128B line

        sC[warp][lane] = make_float4(c[0], c[1], c[2], c[3]);
    }
    __syncwarp();

    // ---- stage out (per warp): regenerate outputs, coalesced, streaming ----
    // f = lane + 32*i: column group f&15 == lane&15 (constant), row f>>4 varies.
    {
        const int cgrp = lane & 15;
        const float4 q0 = Wout4[4 * cgrp + 0];
        const float4 q1 = Wout4[4 * cgrp + 1];
        const float4 q2 = Wout4[4 * cgrp + 2];
        const float4 q3 = Wout4[4 * cgrp + 3];

        float4* gout = reinterpret_cast<float4*>(zq) + (size_t)rowBase * 16;
        #pragma unroll
        for (int i = 0; i < 16; i++) {
            int f = lane + i * 32;
            int r = f >> 4;
            float4 cr = sC[warp][r];           // broadcast LDS.128 (2 rows/warp)
            float4 o;
            o.x = fmaf(cr.x, q0.x, fmaf(cr.y, q0.y, fmaf(cr.z, q0.z, cr.w * q0.w)));
            o.y = fmaf(cr.x, q1.x, fmaf(cr.y, q1.y, fmaf(cr.z, q1.z, cr.w * q1.w)));
            o.z = fmaf(cr.x, q2.x, fmaf(cr.y, q2.y, fmaf(cr.z, q2.z, cr.w * q2.w)));
            o.w = fmaf(cr.x, q3.x, fmaf(cr.y, q3.y, fmaf(cr.z, q3.z, cr.w * q3.w)));
            __stcs(&gout[f], o);
        }
    }

    // ---- last-block finalize (fused; no second launch) ----
    __threadfence();       // every thread: make its hist REDs globally visible
    __syncthreads();       // all warps of this block done + fenced
    if (t == 0) {
        unsigned int v = atomicAdd(&g_done, 1u);
        isLast = (v == gridDim.x - 1);
    }
    __syncthreads();
    if (!isLast) return;

    __threadfence();   // acquire: all blocks' hist atomics visible
    float term = 0.f, nz = 0.f;
    #pragma unroll
    for (int i = t; i < NUM_CODES; i += TPB) {
        int cnt = g_hist[i << HPAD];
        g_hist[i << HPAD] = 0;                        // reset for next replay
        float p = (float)cnt * invB;
        term += p * logf(p + 1e-10f);
        nz   += (cnt > 0) ? 1.0f : 0.0f;
    }
    #pragma unroll
    for (int o = 16; o > 0; o >>= 1) {
        term += __shfl_down_sync(0xFFFFFFFFu, term, o);
        nz   += __shfl_down_sync(0xFFFFFFFFu, nz, o);
    }
    if ((t & 31) == 0) { red[t >> 5] = term; red[4 + (t >> 5)] = nz; }
    __syncthreads();
    if (t == 0) {
        float s = red[0] + red[1] + red[2] + red[3];
        float n = red[4] + red[5] + red[6] + red[7];
        scal[0] = 0.0f;                  // commitment_loss
        scal[1] = 0.0f;                  // codebook_loss
        scal[2] = expf(-s);              // perplexity
        scal[3] = n * (1.0f / 1024.0f);  // utilization
        g_done = 0;                      // reset for next replay
    }
}

// ---------------------------------------------------------------------------
extern "C" void kernel_launch(void* const* d_in, const int* in_sizes, int n_in,
                              void* d_out, int out_size) {
    const float* ze   = (const float*)d_in[0];  // (B, 64)
    const float* Win  = (const float*)d_in[1];  // (4, 64)
    const float* Wout = (const float*)d_in[2];  // (64, 4)

    const int B = in_sizes[0] / 64;
    float* out  = (float*)d_out;
    float* zq   = out;                       // B*64
    float* idxf = out + (size_t)B * 64;      // B
    float* scal = idxf + B;                  // 4 scalars

    const int grid = B / TPB;                // 524288 / 128 = 4096

    fsq_main<<<grid, TPB>>>(ze, Win, (const float4*)Wout,
                            zq, idxf, scal, 1.0f / (float)B);
}